// round 2
// baseline (speedup 1.0000x reference)
#include <cuda_runtime.h>
#include <cuda_bf16.h>
#include <math.h>

// Problem constants
#define B 16
#define C 128
#define H 64
#define W 64
#define HW (H*W)          // 4096
#define OUT 64
#define CR 16
#define RE 8
#define H2 128
#define W2 128

// -------- scratch (static __device__, no allocs) --------
__device__ float g_pooled[B*C];
__device__ float g_wk[B*C*9];
__device__ float g_t1[B*C*HW];
__device__ float g_a[B*C*HW];
__device__ float g_b[B*C*HW];
__device__ float g_fused[B*C*HW];
__device__ float g_wcomb[256*C*9];       // folded up_w1 x up_w2: [oc=o*4+pos][cin][tap]
__device__ float g_re[B*RE*H2*W2];

// ============================================================
// 1) Global average pool: one block per (b,c)
// ============================================================
__global__ void pool_kernel(const float* __restrict__ x, float* __restrict__ pooled) {
    int bc = blockIdx.x;
    const float* p = x + (size_t)bc * HW;
    float s = 0.f;
    for (int i = threadIdx.x; i < HW; i += 256) s += p[i];
    __shared__ float sm[256];
    sm[threadIdx.x] = s;
    __syncthreads();
    for (int o = 128; o > 0; o >>= 1) {
        if (threadIdx.x < o) sm[threadIdx.x] += sm[threadIdx.x + o];
        __syncthreads();
    }
    if (threadIdx.x == 0) pooled[bc] = sm[0] * (1.f / (float)HW);
}

// ============================================================
// 2) MLP + softmax -> per (b,c) 3x3 kernel weights. grid=B, block=128
// ============================================================
__global__ void mlp_kernel(const float* __restrict__ pooled,
                           const float* __restrict__ w1,   // [CR, C]
                           const float* __restrict__ w2,   // [9C, CR]
                           float* __restrict__ wk) {       // [B, C, 9]
    int b = blockIdx.x;
    int t = threadIdx.x;
    __shared__ float sp[C], sh[CR];
    sp[t] = pooled[b * C + t];
    __syncthreads();
    if (t < CR) {
        float acc = 0.f;
        #pragma unroll 8
        for (int c = 0; c < C; c++) acc += sp[c] * w1[t * C + c];
        // exact gelu
        sh[t] = 0.5f * acc * (1.f + erff(acc * 0.70710678118654752440f));
    }
    __syncthreads();
    // thread t handles channel c = t
    float lg[9];
    float mx = -1e30f;
    #pragma unroll
    for (int k = 0; k < 9; k++) {
        float acc = 0.f;
        #pragma unroll
        for (int j = 0; j < CR; j++) acc += sh[j] * w2[(t * 9 + k) * CR + j];
        lg[k] = acc;
        mx = fmaxf(mx, acc);
    }
    float s = 0.f;
    #pragma unroll
    for (int k = 0; k < 9; k++) { lg[k] = expf(lg[k] - mx); s += lg[k]; }
    float inv = 1.f / s;
    #pragma unroll
    for (int k = 0; k < 9; k++) wk[(b * C + t) * 9 + k] = lg[k] * inv;
}

// ============================================================
// 3) dsc apply: depthwise dynamic 3x3 + residual (+optional relu)
//    one block per (b,c), smem-tiled 66x66
// ============================================================
__global__ void dsc_apply_kernel(const float* __restrict__ x,
                                 const float* __restrict__ wk,
                                 float* __restrict__ out, int do_relu) {
    int bc = blockIdx.x;
    const float* xp = x + (size_t)bc * HW;
    __shared__ float tile[66][66];
    __shared__ float w[9];
    int t = threadIdx.x;
    if (t < 9) w[t] = wk[bc * 9 + t];
    for (int i = t; i < 66 * 66; i += 256) {
        int r = i / 66, c = i % 66;
        int rr = r - 1, cc = c - 1;
        tile[r][c] = (rr >= 0 && rr < H && cc >= 0 && cc < W) ? xp[rr * W + cc] : 0.f;
    }
    __syncthreads();
    float* op = out + (size_t)bc * HW;
    for (int i = t; i < HW; i += 256) {
        int r = i >> 6, c = i & 63;
        float acc = tile[r + 1][c + 1];   // residual
        #pragma unroll
        for (int kh = 0; kh < 3; kh++)
            #pragma unroll
            for (int kw = 0; kw < 3; kw++)
                acc += w[kh * 3 + kw] * tile[r + kh][c + kw];
        op[i] = do_relu ? fmaxf(acc, 0.f) : acc;
    }
}

// ============================================================
// 4) fused 1x1 conv over concat(a,b): per-batch GEMM M=128,N=4096,K=256
//    grid (N/64, M/64, B), block 256 (16x16, 4x4 micro)
// ============================================================
__global__ void fuse_gemm_kernel(const float* __restrict__ A,
                                 const float* __restrict__ Bb,
                                 const float* __restrict__ Wal,   // [128, 256]
                                 float* __restrict__ out) {
    int b = blockIdx.z;
    int m0 = blockIdx.y * 64, n0 = blockIdx.x * 64;
    __shared__ float Ws[16][64];
    __shared__ float Xs[16][68];
    float acc[4][4] = {};
    int tx = threadIdx.x % 16, ty = threadIdx.x / 16;
    for (int k0 = 0; k0 < 256; k0 += 16) {
        for (int i = threadIdx.x; i < 16 * 64; i += 256) {
            int kk = i >> 6, mm = i & 63;
            Ws[kk][mm] = Wal[(m0 + mm) * 256 + k0 + kk];
        }
        for (int i = threadIdx.x; i < 16 * 64; i += 256) {
            int kk = i >> 6, nn = i & 63;
            int k = k0 + kk;
            const float* src = (k < C) ? A : Bb;
            int kc = k & (C - 1);
            Xs[kk][nn] = src[((size_t)b * C + kc) * HW + n0 + nn];
        }
        __syncthreads();
        #pragma unroll
        for (int kk = 0; kk < 16; kk++) {
            float wv[4], xv[4];
            #pragma unroll
            for (int i = 0; i < 4; i++) wv[i] = Ws[kk][ty * 4 + i];
            #pragma unroll
            for (int j = 0; j < 4; j++) xv[j] = Xs[kk][tx * 4 + j];
            #pragma unroll
            for (int i = 0; i < 4; i++)
                #pragma unroll
                for (int j = 0; j < 4; j++) acc[i][j] += wv[i] * xv[j];
        }
        __syncthreads();
    }
    #pragma unroll
    for (int i = 0; i < 4; i++)
        #pragma unroll
        for (int j = 0; j < 4; j++)
            out[((size_t)b * C + m0 + ty * 4 + i) * HW + n0 + tx * 4 + j] = acc[i][j];
}

// ============================================================
// 5) fold up_w2 into up_w1 (pixel-shuffle-aware):
//    Wcomb[oc= o*4+pos][cin][tap] = sum_ci up_w2[o,ci]*up_w1[ci*4+pos, cin, tap]
// ============================================================
__global__ void wcomb_kernel(const float* __restrict__ up_w1,   // [512,128,3,3]
                             const float* __restrict__ up_w2) { // [64,128]
    int idx = blockIdx.x * 256 + threadIdx.x;
    if (idx >= 256 * C * 9) return;
    int t = idx % 9;
    int cin = (idx / 9) % C;
    int oc = idx / (9 * C);
    int o = oc >> 2, pos = oc & 3;
    float acc = 0.f;
    #pragma unroll 8
    for (int ci = 0; ci < C; ci++)
        acc += up_w2[o * C + ci] * up_w1[((size_t)(ci * 4 + pos) * C + cin) * 9 + t];
    g_wcomb[idx] = acc;
}

// ============================================================
// 6) big conv 3x3: fused[B,128,64,64] x Wcomb[256,128,9] -> scatter
//    directly into d_out as up[B,64,128,128] (pixel shuffle fused).
//    block: 256 thr (4oc x 4pix micro). tile: 64 oc x 8x8 pixels.
//    grid: (64 spatial tiles, 4 oc tiles, B)
// ============================================================
__global__ void bigconv_kernel(const float* __restrict__ fin,
                               float* __restrict__ outp) {
    int b = blockIdx.z;
    int octile = blockIdx.y;            // 0..3 -> oc base 64*octile
    int st = blockIdx.x;                // 0..63
    int ty0 = (st >> 3) * 8, tx0 = (st & 7) * 8;

    __shared__ float Xs[8][10][10];
    __shared__ float Ws[64][72];

    int tid = threadIdx.x;
    int tpix = tid & 15;                // pixel group
    int toc = tid >> 4;                 // oc group
    int px0 = (tpix * 4) & 7;
    int py = tpix >> 1;

    float acc[4][4] = {};

    for (int k0 = 0; k0 < C; k0 += 8) {
        // load input patch [8 cin][10][10]
        for (int i = tid; i < 8 * 100; i += 256) {
            int cc = i / 100, rem = i % 100;
            int r = rem / 10, c = rem % 10;
            int gy = ty0 + r - 1, gx = tx0 + c - 1;
            float v = 0.f;
            if (gy >= 0 && gy < H && gx >= 0 && gx < W)
                v = fin[((size_t)b * C + k0 + cc) * HW + gy * W + gx];
            Xs[cc][r][c] = v;
        }
        // load weights [64 oc][8 cin * 9 taps]
        for (int i = tid; i < 64 * 72; i += 256) {
            int ol = i / 72, kt = i % 72;
            int cc = kt / 9, t = kt % 9;
            Ws[ol][kt] = g_wcomb[((size_t)(octile * 64 + ol) * C + k0 + cc) * 9 + t];
        }
        __syncthreads();
        #pragma unroll
        for (int cc = 0; cc < 8; cc++) {
            #pragma unroll
            for (int t = 0; t < 9; t++) {
                int kh = t / 3, kw = t % 3;
                float wv[4], xv[4];
                #pragma unroll
                for (int i = 0; i < 4; i++) wv[i] = Ws[toc * 4 + i][cc * 9 + t];
                #pragma unroll
                for (int j = 0; j < 4; j++) xv[j] = Xs[cc][py + kh][px0 + j + kw];
                #pragma unroll
                for (int i = 0; i < 4; i++)
                    #pragma unroll
                    for (int j = 0; j < 4; j++) acc[i][j] += wv[i] * xv[j];
            }
        }
        __syncthreads();
    }
    // scatter: oc = o*4 + (2*r1+r2); out pixel (2y+r1, 2x+r2)
    #pragma unroll
    for (int i = 0; i < 4; i++) {
        int oc = octile * 64 + toc * 4 + i;
        int o = oc >> 2, pos = oc & 3;
        int r1 = pos >> 1, r2 = pos & 1;
        #pragma unroll
        for (int j = 0; j < 4; j++) {
            int gy = ty0 + py, gx = tx0 + px0 + j;
            int y = gy * 2 + r1, x = gx * 2 + r2;
            outp[(((size_t)b * OUT + o) * H2 + y) * W2 + x] = acc[i][j];
        }
    }
}

// ============================================================
// 7) refine conv1: 64->8 3x3 at 128x128, relu. block handles 16x16 pixels,
//    each thread 1 pixel x 8 out-ch. grid (64 spatial, B)
// ============================================================
__global__ void reconv1_kernel(const float* __restrict__ up,
                               const float* __restrict__ w) { // [8,64,3,3]
    int b = blockIdx.y;
    int st = blockIdx.x;
    int gy0 = (st >> 3) * 16, gx0 = (st & 7) * 16;
    __shared__ float Xs[8][18][18];
    __shared__ float Ws[8][72];
    int tid = threadIdx.x;
    int py = tid >> 4, px = tid & 15;
    float acc[8] = {};
    for (int k0 = 0; k0 < OUT; k0 += 8) {
        for (int i = tid; i < 8 * 324; i += 256) {
            int cc = i / 324, rem = i % 324;
            int r = rem / 18, c = rem % 18;
            int gy = gy0 + r - 1, gx = gx0 + c - 1;
            float v = 0.f;
            if (gy >= 0 && gy < H2 && gx >= 0 && gx < W2)
                v = up[(((size_t)b * OUT + k0 + cc) * H2 + gy) * W2 + gx];
            Xs[cc][r][c] = v;
        }
        for (int i = tid; i < 8 * 72; i += 256) {
            int rch = i / 72, kt = i % 72;
            int cc = kt / 9, t = kt % 9;
            Ws[rch][kt] = w[((rch * OUT) + k0 + cc) * 9 + t];
        }
        __syncthreads();
        #pragma unroll
        for (int cc = 0; cc < 8; cc++) {
            #pragma unroll
            for (int t = 0; t < 9; t++) {
                int kh = t / 3, kw = t % 3;
                float xv = Xs[cc][py + kh][px + kw];
                #pragma unroll
                for (int r = 0; r < 8; r++) acc[r] += Ws[r][cc * 9 + t] * xv;
            }
        }
        __syncthreads();
    }
    #pragma unroll
    for (int r = 0; r < 8; r++)
        g_re[(((size_t)b * RE + r) * H2 + gy0 + py) * W2 + gx0 + px] = fmaxf(acc[r], 0.f);
}

// ============================================================
// 8) refine conv2 + residual add into d_out: 8->64 3x3 at 128x128.
//    grid (64 spatial, 4 octiles, B); thread: 1 pixel x 16 oc
// ============================================================
__global__ void reconv2_kernel(const float* __restrict__ w,   // [64,8,3,3]
                               float* __restrict__ outp) {
    int b = blockIdx.z;
    int octile = blockIdx.y;   // 16 oc each
    int st = blockIdx.x;
    int gy0 = (st >> 3) * 16, gx0 = (st & 7) * 16;
    __shared__ float Xs[8][18][18];
    __shared__ float Ws[16][72];
    int tid = threadIdx.x;
    int py = tid >> 4, px = tid & 15;
    for (int i = tid; i < 8 * 324; i += 256) {
        int cc = i / 324, rem = i % 324;
        int r = rem / 18, c = rem % 18;
        int gy = gy0 + r - 1, gx = gx0 + c - 1;
        float v = 0.f;
        if (gy >= 0 && gy < H2 && gx >= 0 && gx < W2)
            v = g_re[(((size_t)b * RE + cc) * H2 + gy) * W2 + gx];
        Xs[cc][r][c] = v;
    }
    for (int i = tid; i < 16 * 72; i += 256) {
        int o = i / 72, kt = i % 72;
        int cc = kt / 9, t = kt % 9;
        Ws[o][kt] = w[((octile * 16 + o) * RE + cc) * 9 + t];
    }
    __syncthreads();
    float acc[16] = {};
    #pragma unroll
    for (int cc = 0; cc < 8; cc++) {
        #pragma unroll
        for (int t = 0; t < 9; t++) {
            int kh = t / 3, kw = t % 3;
            float xv = Xs[cc][py + kh][px + kw];
            #pragma unroll
            for (int o = 0; o < 16; o++) acc[o] += Ws[o][cc * 9 + t] * xv;
        }
    }
    #pragma unroll
    for (int o = 0; o < 16; o++) {
        size_t idx = (((size_t)b * OUT + octile * 16 + o) * H2 + gy0 + py) * W2 + gx0 + px;
        outp[idx] = outp[idx] + acc[o];
    }
}

// ============================================================
extern "C" void kernel_launch(void* const* d_in, const int* in_sizes, int n_in,
                              void* d_out, int out_size) {
    const float* x1     = (const float*)d_in[0];
    const float* x2     = (const float*)d_in[1];
    const float* d1_w1  = (const float*)d_in[2];
    const float* d1_w2  = (const float*)d_in[3];
    const float* d2_w1  = (const float*)d_in[4];
    const float* d2_w2  = (const float*)d_in[5];
    const float* alignw = (const float*)d_in[6];
    const float* up_w1  = (const float*)d_in[7];
    const float* up_w2  = (const float*)d_in[8];
    const float* re_w1  = (const float*)d_in[9];
    const float* re_w2  = (const float*)d_in[10];
    float* outp = (float*)d_out;

    void *pv, *wkv, *t1v, *av, *bv, *fv;
    cudaGetSymbolAddress(&pv, g_pooled);
    cudaGetSymbolAddress(&wkv, g_wk);
    cudaGetSymbolAddress(&t1v, g_t1);
    cudaGetSymbolAddress(&av, g_a);
    cudaGetSymbolAddress(&bv, g_b);
    cudaGetSymbolAddress(&fv, g_fused);
    float* pooled = (float*)pv;
    float* wkb    = (float*)wkv;
    float* t1     = (float*)t1v;
    float* a      = (float*)av;
    float* bb     = (float*)bv;
    float* fused  = (float*)fv;

    // fold up_w2 into up_w1 (independent of data path)
    wcomb_kernel<<<(256 * C * 9 + 255) / 256, 256>>>(up_w1, up_w2);

    // dynamic_block(x1) -> a
    pool_kernel<<<B * C, 256>>>(x1, pooled);
    mlp_kernel<<<B, C>>>(pooled, d1_w1, d1_w2, wkb);
    dsc_apply_kernel<<<B * C, 256>>>(x1, wkb, t1, 1);
    pool_kernel<<<B * C, 256>>>(t1, pooled);
    mlp_kernel<<<B, C>>>(pooled, d2_w1, d2_w2, wkb);
    dsc_apply_kernel<<<B * C, 256>>>(t1, wkb, a, 0);

    // dynamic_block(x2) -> bb
    pool_kernel<<<B * C, 256>>>(x2, pooled);
    mlp_kernel<<<B, C>>>(pooled, d1_w1, d1_w2, wkb);
    dsc_apply_kernel<<<B * C, 256>>>(x2, wkb, t1, 1);
    pool_kernel<<<B * C, 256>>>(t1, pooled);
    mlp_kernel<<<B, C>>>(pooled, d2_w1, d2_w2, wkb);
    dsc_apply_kernel<<<B * C, 256>>>(t1, wkb, bb, 0);

    // align 1x1 over concat
    fuse_gemm_kernel<<<dim3(HW / 64, C / 64, B), 256>>>(a, bb, alignw, fused);

    // conv3x3 (folded with up_w2) + pixel shuffle, scatter into d_out
    bigconv_kernel<<<dim3(64, 4, B), 256>>>(fused, outp);

    // refine
    reconv1_kernel<<<dim3(64, B), 256>>>(outp, re_w1);
    reconv2_kernel<<<dim3(64, 4, B), 256>>>(re_w2, outp);
}

// round 5
// speedup vs baseline: 1.9007x; 1.9007x over previous
#include <cuda_runtime.h>
#include <cuda_bf16.h>
#include <cstdint>
#include <math.h>

// Problem constants
#define B 16
#define C 128
#define H 64
#define W 64
#define HW (H*W)          // 4096
#define OUT 64
#define CR 16
#define RE 8
#define H2 128
#define W2 128

// -------- scratch (static __device__, no allocs) --------
__device__ float g_pooled[B*C];
__device__ float g_wk[B*C*9];
__device__ float g_t1[B*C*HW];
__device__ float g_a[B*C*HW];
__device__ float g_b[B*C*HW];
__device__ float g_fused[B*C*HW];
// folded up_w1 x up_w2 (tf32-rounded), permuted K: [oc][k'], k' = cb*288 + tap*32 + (cin%32)
__device__ float g_wcomb[256*C*9];
__device__ float g_re[B*RE*H2*W2];

__device__ __forceinline__ float to_tf32(float f) {
    uint32_t r; asm("cvt.rna.tf32.f32 %0, %1;" : "=r"(r) : "f"(f));
    return __uint_as_float(r);
}

// warp mma: D[16x8] += A[16x8 tf32] * B[8x8 tf32]
__device__ __forceinline__ void mma_tf32(float* c, const uint32_t* a, uint32_t b0, uint32_t b1) {
    asm volatile(
        "mma.sync.aligned.m16n8k8.row.col.f32.tf32.tf32.f32 "
        "{%0,%1,%2,%3}, {%4,%5,%6,%7}, {%8,%9}, {%0,%1,%2,%3};\n"
        : "+f"(c[0]), "+f"(c[1]), "+f"(c[2]), "+f"(c[3])
        : "r"(a[0]), "r"(a[1]), "r"(a[2]), "r"(a[3]), "r"(b0), "r"(b1));
}

// ============================================================
// 1) Global average pool
// ============================================================
__global__ void pool_kernel(const float* __restrict__ x, float* __restrict__ pooled) {
    int bc = blockIdx.x;
    const float* p = x + (size_t)bc * HW;
    float s = 0.f;
    for (int i = threadIdx.x; i < HW; i += 256) s += p[i];
    __shared__ float sm[256];
    sm[threadIdx.x] = s;
    __syncthreads();
    for (int o = 128; o > 0; o >>= 1) {
        if (threadIdx.x < o) sm[threadIdx.x] += sm[threadIdx.x + o];
        __syncthreads();
    }
    if (threadIdx.x == 0) pooled[bc] = sm[0] * (1.f / (float)HW);
}

// ============================================================
// 2) MLP + softmax
// ============================================================
__global__ void mlp_kernel(const float* __restrict__ pooled,
                           const float* __restrict__ w1,
                           const float* __restrict__ w2,
                           float* __restrict__ wk) {
    int b = blockIdx.x;
    int t = threadIdx.x;
    __shared__ float sp[C], sh[CR];
    sp[t] = pooled[b * C + t];
    __syncthreads();
    if (t < CR) {
        float acc = 0.f;
        #pragma unroll 8
        for (int c = 0; c < C; c++) acc += sp[c] * w1[t * C + c];
        sh[t] = 0.5f * acc * (1.f + erff(acc * 0.70710678118654752440f));
    }
    __syncthreads();
    float lg[9];
    float mx = -1e30f;
    #pragma unroll
    for (int k = 0; k < 9; k++) {
        float acc = 0.f;
        #pragma unroll
        for (int j = 0; j < CR; j++) acc += sh[j] * w2[(t * 9 + k) * CR + j];
        lg[k] = acc;
        mx = fmaxf(mx, acc);
    }
    float s = 0.f;
    #pragma unroll
    for (int k = 0; k < 9; k++) { lg[k] = expf(lg[k] - mx); s += lg[k]; }
    float inv = 1.f / s;
    #pragma unroll
    for (int k = 0; k < 9; k++) wk[(b * C + t) * 9 + k] = lg[k] * inv;
}

// ============================================================
// 3) dsc apply: depthwise dynamic 3x3 + residual (+optional relu)
// ============================================================
__global__ void dsc_apply_kernel(const float* __restrict__ x,
                                 const float* __restrict__ wk,
                                 float* __restrict__ out, int do_relu) {
    int bc = blockIdx.x;
    const float* xp = x + (size_t)bc * HW;
    __shared__ float tile[66][66];
    __shared__ float w[9];
    int t = threadIdx.x;
    if (t < 9) w[t] = wk[bc * 9 + t];
    for (int i = t; i < 66 * 66; i += 256) {
        int r = i / 66, c = i % 66;
        int rr = r - 1, cc = c - 1;
        tile[r][c] = (rr >= 0 && rr < H && cc >= 0 && cc < W) ? xp[rr * W + cc] : 0.f;
    }
    __syncthreads();
    float* op = out + (size_t)bc * HW;
    for (int i = t; i < HW; i += 256) {
        int r = i >> 6, c = i & 63;
        float acc = tile[r + 1][c + 1];
        #pragma unroll
        for (int kh = 0; kh < 3; kh++)
            #pragma unroll
            for (int kw = 0; kw < 3; kw++)
                acc += w[kh * 3 + kw] * tile[r + kh][c + kw];
        op[i] = do_relu ? fmaxf(acc, 0.f) : acc;
    }
}

// ============================================================
// 4) fused 1x1 conv GEMM (fp32 SIMT)
// ============================================================
__global__ void fuse_gemm_kernel(const float* __restrict__ A,
                                 const float* __restrict__ Bb,
                                 const float* __restrict__ Wal,
                                 float* __restrict__ out) {
    int b = blockIdx.z;
    int m0 = blockIdx.y * 64, n0 = blockIdx.x * 64;
    __shared__ float Ws[16][64];
    __shared__ float Xs[16][68];
    float acc[4][4] = {};
    int tx = threadIdx.x % 16, ty = threadIdx.x / 16;
    for (int k0 = 0; k0 < 256; k0 += 16) {
        for (int i = threadIdx.x; i < 16 * 64; i += 256) {
            int kk = i >> 6, mm = i & 63;
            Ws[kk][mm] = Wal[(m0 + mm) * 256 + k0 + kk];
        }
        for (int i = threadIdx.x; i < 16 * 64; i += 256) {
            int kk = i >> 6, nn = i & 63;
            int k = k0 + kk;
            const float* src = (k < C) ? A : Bb;
            int kc = k & (C - 1);
            Xs[kk][nn] = src[((size_t)b * C + kc) * HW + n0 + nn];
        }
        __syncthreads();
        #pragma unroll
        for (int kk = 0; kk < 16; kk++) {
            float wv[4], xv[4];
            #pragma unroll
            for (int i = 0; i < 4; i++) wv[i] = Ws[kk][ty * 4 + i];
            #pragma unroll
            for (int j = 0; j < 4; j++) xv[j] = Xs[kk][tx * 4 + j];
            #pragma unroll
            for (int i = 0; i < 4; i++)
                #pragma unroll
                for (int j = 0; j < 4; j++) acc[i][j] += wv[i] * xv[j];
        }
        __syncthreads();
    }
    #pragma unroll
    for (int i = 0; i < 4; i++)
        #pragma unroll
        for (int j = 0; j < 4; j++)
            out[((size_t)b * C + m0 + ty * 4 + i) * HW + n0 + tx * 4 + j] = acc[i][j];
}

// ============================================================
// 5) fold up_w2 into up_w1 (tf32-rounded), permuted K layout
// ============================================================
__global__ void wcomb_kernel(const float* __restrict__ up_w1,   // [512,128,3,3]
                             const float* __restrict__ up_w2) { // [64,128]
    int idx = blockIdx.x * 256 + threadIdx.x;
    if (idx >= 256 * C * 9) return;
    int kprime = idx % 1152;
    int oc = idx / 1152;
    int cb = kprime / 288;
    int rem = kprime % 288;
    int tap = rem / 32;
    int cin = cb * 32 + (rem & 31);
    int o = oc >> 2, pos = oc & 3;
    float acc = 0.f;
    #pragma unroll 8
    for (int ci = 0; ci < C; ci++)
        acc += up_w2[o * C + ci] * up_w1[((size_t)(ci * 4 + pos) * C + cin) * 9 + tap];
    g_wcomb[idx] = to_tf32(acc);
}

// ============================================================
// 6) big conv 3x3 via tf32 mma.sync (implicit GEMM, A from halo):
//    D[128 px, 128 oc] per CTA; grid (32 spatial tiles, 2 oc halves, B).
//    Pixel tile 8 rows x 16 cols. K = 1152 in chunks of 32 (cin-block x tap).
//    A fragments read straight from the tf32-rounded halo tile (address-only
//    im2col). Epilogue scatters pixel-shuffled straight into d_out.
// ============================================================
__global__ __launch_bounds__(256, 2)
void bigconv_mma_kernel(const float* __restrict__ fin, float* __restrict__ outp) {
    __shared__ float XH[32 * 201];   // [cin 32][halo 10x18, row stride 20]
    __shared__ float Bs[128 * 36];   // [oc 128][k 32 + pad 4]

    int tid = threadIdx.x;
    int wid = tid >> 5, lane = tid & 31;
    int b = blockIdx.z, oh = blockIdx.y, st = blockIdx.x;
    int ty0 = (st >> 2) * 8, tx0 = (st & 3) * 16;
    int mg = wid >> 1;      // 0..3  (32-px group)
    int ng = wid & 1;       // 0..1  (64-oc group)

    // halo row offsets for the 4 A-fragment pixel rows (a0/a2 and a1/a3, mt 0/1)
    int h0[2], h1[2];
    #pragma unroll
    for (int mt = 0; mt < 2; mt++) {
        int p0 = mg * 32 + mt * 16 + (lane >> 2);
        int p1 = p0 + 8;
        h0[mt] = (p0 >> 4) * 20 + (p0 & 15);
        h1[mt] = (p1 >> 4) * 20 + (p1 & 15);
    }

    float acc[2][8][4];
    #pragma unroll
    for (int mt = 0; mt < 2; mt++)
        #pragma unroll
        for (int nt = 0; nt < 8; nt++)
            #pragma unroll
            for (int i = 0; i < 4; i++) acc[mt][nt][i] = 0.f;

    const float* wbase = g_wcomb + (size_t)(oh * 128) * 1152;

    for (int cb = 0; cb < 4; cb++) {
        for (int tap = 0; tap < 9; tap++) {
            __syncthreads();   // previous chunk's compute finished
            if (tap == 0) {
                // load halo for this cin-block (tf32-rounded)
                for (int i = tid; i < 32 * 180; i += 256) {
                    int cw = i / 180, rem = i % 180, r = rem / 18, c = rem % 18;
                    int gy = ty0 + r - 1, gx = tx0 + c - 1;
                    float v = 0.f;
                    if (gy >= 0 && gy < H && gx >= 0 && gx < W)
                        v = fin[((size_t)b * C + cb * 32 + cw) * HW + gy * W + gx];
                    XH[cw * 201 + r * 20 + c] = to_tf32(v);
                }
            }
            // load B chunk [128 oc][32 k] (already tf32-rounded)
            {
                const float4* src = (const float4*)(wbase + cb * 288 + tap * 32);
                int n = tid >> 3, q = tid & 7;
                #pragma unroll
                for (int r = 0; r < 4; r++) {
                    int nn = n + 32 * r;
                    float4 v = src[(size_t)nn * 288 + q];
                    float* d = &Bs[nn * 36 + q * 4];
                    d[0] = v.x; d[1] = v.y; d[2] = v.z; d[3] = v.w;
                }
            }
            __syncthreads();

            int d = (tap / 3) * 20 + (tap % 3);
            #pragma unroll
            for (int kk = 0; kk < 4; kk++) {
                uint32_t afr[2][4];
                int c0 = (kk * 8 + (lane & 3)) * 201 + d;
                #pragma unroll
                for (int mt = 0; mt < 2; mt++) {
                    afr[mt][0] = __float_as_uint(XH[c0 + h0[mt]]);
                    afr[mt][1] = __float_as_uint(XH[c0 + h1[mt]]);
                    afr[mt][2] = __float_as_uint(XH[c0 + 4 * 201 + h0[mt]]);
                    afr[mt][3] = __float_as_uint(XH[c0 + 4 * 201 + h1[mt]]);
                }
                #pragma unroll
                for (int nt = 0; nt < 8; nt++) {
                    int nb = (ng * 64 + nt * 8 + (lane >> 2)) * 36 + kk * 8 + (lane & 3);
                    uint32_t b0 = __float_as_uint(Bs[nb]);
                    uint32_t b1 = __float_as_uint(Bs[nb + 4]);
                    mma_tf32(acc[0][nt], afr[0], b0, b1);
                    mma_tf32(acc[1][nt], afr[1], b0, b1);
                }
            }
        }
    }

    // epilogue: scatter with fused pixel shuffle.
    // c mapping: rows r=lane>>2 (+8 for i>=2), cols 2*(lane&3)+(i&1)
    #pragma unroll
    for (int mt = 0; mt < 2; mt++) {
        #pragma unroll
        for (int nt = 0; nt < 8; nt++) {
            #pragma unroll
            for (int i = 0; i < 4; i++) {
                int px = mg * 32 + mt * 16 + (lane >> 2) + ((i >> 1) * 8);
                int oc = oh * 128 + ng * 64 + nt * 8 + 2 * (lane & 3) + (i & 1);
                int gy = ty0 + (px >> 4), gx = tx0 + (px & 15);
                int o = oc >> 2, r1 = (oc >> 1) & 1, r2 = oc & 1;
                outp[(((size_t)b * OUT + o) * H2 + 2 * gy + r1) * W2 + 2 * gx + r2] =
                    acc[mt][nt][i];
            }
        }
    }
}

// ============================================================
// 7) refine conv1: 64->8 3x3 at 128x128, relu
// ============================================================
__global__ void reconv1_kernel(const float* __restrict__ up,
                               const float* __restrict__ w) {
    int b = blockIdx.y;
    int st = blockIdx.x;
    int gy0 = (st >> 3) * 16, gx0 = (st & 7) * 16;
    __shared__ float Xs[8][18][18];
    __shared__ float Ws[8][72];
    int tid = threadIdx.x;
    int py = tid >> 4, px = tid & 15;
    float acc[8] = {};
    for (int k0 = 0; k0 < OUT; k0 += 8) {
        for (int i = tid; i < 8 * 324; i += 256) {
            int cc = i / 324, rem = i % 324;
            int r = rem / 18, c = rem % 18;
            int gy = gy0 + r - 1, gx = gx0 + c - 1;
            float v = 0.f;
            if (gy >= 0 && gy < H2 && gx >= 0 && gx < W2)
                v = up[(((size_t)b * OUT + k0 + cc) * H2 + gy) * W2 + gx];
            Xs[cc][r][c] = v;
        }
        for (int i = tid; i < 8 * 72; i += 256) {
            int rch = i / 72, kt = i % 72;
            int cc = kt / 9, t = kt % 9;
            Ws[rch][kt] = w[((rch * OUT) + k0 + cc) * 9 + t];
        }
        __syncthreads();
        #pragma unroll
        for (int cc = 0; cc < 8; cc++) {
            #pragma unroll
            for (int t = 0; t < 9; t++) {
                int kh = t / 3, kw = t % 3;
                float xv = Xs[cc][py + kh][px + kw];
                #pragma unroll
                for (int r = 0; r < 8; r++) acc[r] += Ws[r][cc * 9 + t] * xv;
            }
        }
        __syncthreads();
    }
    #pragma unroll
    for (int r = 0; r < 8; r++)
        g_re[(((size_t)b * RE + r) * H2 + gy0 + py) * W2 + gx0 + px] = fmaxf(acc[r], 0.f);
}

// ============================================================
// 8) refine conv2 + residual add
// ============================================================
__global__ void reconv2_kernel(const float* __restrict__ w,
                               float* __restrict__ outp) {
    int b = blockIdx.z;
    int octile = blockIdx.y;
    int st = blockIdx.x;
    int gy0 = (st >> 3) * 16, gx0 = (st & 7) * 16;
    __shared__ float Xs[8][18][18];
    __shared__ float Ws[16][72];
    int tid = threadIdx.x;
    int py = tid >> 4, px = tid & 15;
    for (int i = tid; i < 8 * 324; i += 256) {
        int cc = i / 324, rem = i % 324;
        int r = rem / 18, c = rem % 18;
        int gy = gy0 + r - 1, gx = gx0 + c - 1;
        float v = 0.f;
        if (gy >= 0 && gy < H2 && gx >= 0 && gx < W2)
            v = g_re[(((size_t)b * RE + cc) * H2 + gy) * W2 + gx];
        Xs[cc][r][c] = v;
    }
    for (int i = tid; i < 16 * 72; i += 256) {
        int o = i / 72, kt = i % 72;
        int cc = kt / 9, t = kt % 9;
        Ws[o][kt] = w[((octile * 16 + o) * RE + cc) * 9 + t];
    }
    __syncthreads();
    float acc[16] = {};
    #pragma unroll
    for (int cc = 0; cc < 8; cc++) {
        #pragma unroll
        for (int t = 0; t < 9; t++) {
            int kh = t / 3, kw = t % 3;
            float xv = Xs[cc][py + kh][px + kw];
            #pragma unroll
            for (int o = 0; o < 16; o++) acc[o] += Ws[o][cc * 9 + t] * xv;
        }
    }
    #pragma unroll
    for (int o = 0; o < 16; o++) {
        size_t idx = (((size_t)b * OUT + octile * 16 + o) * H2 + gy0 + py) * W2 + gx0 + px;
        outp[idx] = outp[idx] + acc[o];
    }
}

// ============================================================
extern "C" void kernel_launch(void* const* d_in, const int* in_sizes, int n_in,
                              void* d_out, int out_size) {
    const float* x1     = (const float*)d_in[0];
    const float* x2     = (const float*)d_in[1];
    const float* d1_w1  = (const float*)d_in[2];
    const float* d1_w2  = (const float*)d_in[3];
    const float* d2_w1  = (const float*)d_in[4];
    const float* d2_w2  = (const float*)d_in[5];
    const float* alignw = (const float*)d_in[6];
    const float* up_w1  = (const float*)d_in[7];
    const float* up_w2  = (const float*)d_in[8];
    const float* re_w1  = (const float*)d_in[9];
    const float* re_w2  = (const float*)d_in[10];
    float* outp = (float*)d_out;

    void *pv, *wkv, *t1v, *av, *bv, *fv;
    cudaGetSymbolAddress(&pv, g_pooled);
    cudaGetSymbolAddress(&wkv, g_wk);
    cudaGetSymbolAddress(&t1v, g_t1);
    cudaGetSymbolAddress(&av, g_a);
    cudaGetSymbolAddress(&bv, g_b);
    cudaGetSymbolAddress(&fv, g_fused);
    float* pooled = (float*)pv;
    float* wkb    = (float*)wkv;
    float* t1     = (float*)t1v;
    float* a      = (float*)av;
    float* bb     = (float*)bv;
    float* fused  = (float*)fv;

    // fold up_w2 into up_w1 (tf32, permuted-K layout)
    wcomb_kernel<<<(256 * C * 9 + 255) / 256, 256>>>(up_w1, up_w2);

    // dynamic_block(x1) -> a
    pool_kernel<<<B * C, 256>>>(x1, pooled);
    mlp_kernel<<<B, C>>>(pooled, d1_w1, d1_w2, wkb);
    dsc_apply_kernel<<<B * C, 256>>>(x1, wkb, t1, 1);
    pool_kernel<<<B * C, 256>>>(t1, pooled);
    mlp_kernel<<<B, C>>>(pooled, d2_w1, d2_w2, wkb);
    dsc_apply_kernel<<<B * C, 256>>>(t1, wkb, a, 0);

    // dynamic_block(x2) -> bb
    pool_kernel<<<B * C, 256>>>(x2, pooled);
    mlp_kernel<<<B, C>>>(pooled, d1_w1, d1_w2, wkb);
    dsc_apply_kernel<<<B * C, 256>>>(x2, wkb, t1, 1);
    pool_kernel<<<B * C, 256>>>(t1, pooled);
    mlp_kernel<<<B, C>>>(pooled, d2_w1, d2_w2, wkb);
    dsc_apply_kernel<<<B * C, 256>>>(t1, wkb, bb, 0);

    // align 1x1 over concat
    fuse_gemm_kernel<<<dim3(HW / 64, C / 64, B), 256>>>(a, bb, alignw, fused);

    // conv3x3 (folded with up_w2) + pixel shuffle via tf32 mma.sync
    bigconv_mma_kernel<<<dim3(32, 2, B), 256>>>(fused, outp);

    // refine
    reconv1_kernel<<<dim3(64, B), 256>>>(outp, re_w1);
    reconv2_kernel<<<dim3(64, 4, B), 256>>>(re_w2, outp);
}

// round 6
// speedup vs baseline: 2.7667x; 1.4556x over previous
#include <cuda_runtime.h>
#include <cuda_bf16.h>
#include <cstdint>
#include <math.h>

// Problem constants
#define B 16
#define C 128
#define H 64
#define W 64
#define HW (H*W)          // 4096
#define OUT 64
#define CR 16
#define RE 8
#define H2 128
#define W2 128

// -------- scratch (static __device__, no allocs) --------
__device__ float g_pooled[B*C];
__device__ float g_wk[B*C*9];
__device__ float g_t1[B*C*HW];
__device__ float g_a[B*C*HW];
__device__ float g_b[B*C*HW];
__device__ float g_fused[B*C*HW];
// folded up_w1 x up_w2 (tf32-rounded), permuted K: [oc][k'], k' = cb*288 + tap*32 + (cin%32)
__device__ float g_wcomb[256*C*9];
__device__ float g_re[B*RE*H2*W2];

__device__ __forceinline__ float to_tf32(float f) {
    uint32_t r; asm("cvt.rna.tf32.f32 %0, %1;" : "=r"(r) : "f"(f));
    return __uint_as_float(r);
}

// warp mma: D[16x8] += A[16x8 tf32] * B[8x8 tf32]
__device__ __forceinline__ void mma_tf32(float* c, const uint32_t* a, uint32_t b0, uint32_t b1) {
    asm volatile(
        "mma.sync.aligned.m16n8k8.row.col.f32.tf32.tf32.f32 "
        "{%0,%1,%2,%3}, {%4,%5,%6,%7}, {%8,%9}, {%0,%1,%2,%3};\n"
        : "+f"(c[0]), "+f"(c[1]), "+f"(c[2]), "+f"(c[3])
        : "r"(a[0]), "r"(a[1]), "r"(a[2]), "r"(a[3]), "r"(b0), "r"(b1));
}

// ============================================================
// 1) Global average pool (only used for the raw inputs x1/x2)
// ============================================================
__global__ void pool_kernel(const float* __restrict__ x, float* __restrict__ pooled) {
    int bc = blockIdx.x;
    const float* p = x + (size_t)bc * HW;
    float s = 0.f;
    for (int i = threadIdx.x; i < HW; i += 256) s += p[i];
    __shared__ float sm[256];
    sm[threadIdx.x] = s;
    __syncthreads();
    for (int o = 128; o > 0; o >>= 1) {
        if (threadIdx.x < o) sm[threadIdx.x] += sm[threadIdx.x + o];
        __syncthreads();
    }
    if (threadIdx.x == 0) pooled[bc] = sm[0] * (1.f / (float)HW);
}

// ============================================================
// 2) MLP + softmax
// ============================================================
__global__ void mlp_kernel(const float* __restrict__ pooled,
                           const float* __restrict__ w1,
                           const float* __restrict__ w2,
                           float* __restrict__ wk) {
    int b = blockIdx.x;
    int t = threadIdx.x;
    __shared__ float sp[C], sh[CR];
    sp[t] = pooled[b * C + t];
    __syncthreads();
    if (t < CR) {
        float acc = 0.f;
        #pragma unroll 8
        for (int c = 0; c < C; c++) acc += sp[c] * w1[t * C + c];
        sh[t] = 0.5f * acc * (1.f + erff(acc * 0.70710678118654752440f));
    }
    __syncthreads();
    float lg[9];
    float mx = -1e30f;
    #pragma unroll
    for (int k = 0; k < 9; k++) {
        float acc = 0.f;
        #pragma unroll
        for (int j = 0; j < CR; j++) acc += sh[j] * w2[(t * 9 + k) * CR + j];
        lg[k] = acc;
        mx = fmaxf(mx, acc);
    }
    float s = 0.f;
    #pragma unroll
    for (int k = 0; k < 9; k++) { lg[k] = expf(lg[k] - mx); s += lg[k]; }
    float inv = 1.f / s;
    #pragma unroll
    for (int k = 0; k < 9; k++) wk[(b * C + t) * 9 + k] = lg[k] * inv;
}

// ============================================================
// 3) dsc apply: depthwise dynamic 3x3 + residual (+optional relu)
//    4-wide strips per thread; optional fused global-avg-pool of the
//    (post-relu) output into pooled[bc].
// ============================================================
__global__ void dsc_apply_kernel(const float* __restrict__ x,
                                 const float* __restrict__ wk,
                                 float* __restrict__ out, int do_relu,
                                 float* __restrict__ pooled) {
    int bc = blockIdx.x;
    const float* xp = x + (size_t)bc * HW;
    __shared__ float tile[66][67];
    __shared__ float w[9];
    __shared__ float red[256];
    int t = threadIdx.x;
    if (t < 9) w[t] = wk[bc * 9 + t];
    for (int i = t; i < 66 * 66; i += 256) {
        int r = i / 66, c = i % 66;
        int rr = r - 1, cc = c - 1;
        tile[r][c] = (rr >= 0 && rr < H && cc >= 0 && cc < W) ? xp[rr * W + cc] : 0.f;
    }
    __syncthreads();
    float w0 = w[0], w1 = w[1], w2 = w[2], w3 = w[3], w4 = w[4],
          w5 = w[5], w6 = w[6], w7 = w[7], w8 = w[8];
    float* op = out + (size_t)bc * HW;
    float sum = 0.f;
    #pragma unroll
    for (int s = 0; s < 4; s++) {
        int id = t + s * 256;
        int r = id >> 4, c0 = (id & 15) * 4;
        float la[3][6];
        #pragma unroll
        for (int kh = 0; kh < 3; kh++)
            #pragma unroll
            for (int j = 0; j < 6; j++) la[kh][j] = tile[r + kh][c0 + j];
        float4 o;
        float* ov = &o.x;
        #pragma unroll
        for (int j = 0; j < 4; j++) {
            float acc = la[1][j + 1]
                + w0 * la[0][j] + w1 * la[0][j + 1] + w2 * la[0][j + 2]
                + w3 * la[1][j] + w4 * la[1][j + 1] + w5 * la[1][j + 2]
                + w6 * la[2][j] + w7 * la[2][j + 1] + w8 * la[2][j + 2];
            if (do_relu) acc = fmaxf(acc, 0.f);
            ov[j] = acc;
            sum += acc;
        }
        *(float4*)(op + r * 64 + c0) = o;
    }
    if (pooled) {
        red[t] = sum;
        __syncthreads();
        for (int o2 = 128; o2 > 0; o2 >>= 1) {
            if (t < o2) red[t] += red[t + o2];
            __syncthreads();
        }
        if (t == 0) pooled[bc] = red[0] * (1.f / (float)HW);
    }
}

// ============================================================
// 4) fused 1x1 conv over concat(a,b) via tf32 mma:
//    per CTA D[128 px, 128 oc], K=256. grid (32 hw tiles, B).
// ============================================================
__global__ __launch_bounds__(256, 2)
void fuse_mma_kernel(const float* __restrict__ A,
                     const float* __restrict__ Bb,
                     const float* __restrict__ Wal,   // [128, 256]
                     float* __restrict__ out) {
    __shared__ float As[32][136];   // [k][px]
    __shared__ float Bs[128][36];   // [oc][k]
    int tid = threadIdx.x;
    int wid = tid >> 5, lane = tid & 31;
    int b = blockIdx.y;
    int hw0 = blockIdx.x * 128;
    int mg = wid >> 1, ng = wid & 1;

    float acc[2][8][4];
    #pragma unroll
    for (int mt = 0; mt < 2; mt++)
        #pragma unroll
        for (int nt = 0; nt < 8; nt++)
            #pragma unroll
            for (int i = 0; i < 4; i++) acc[mt][nt][i] = 0.f;

    for (int cb = 0; cb < 8; cb++) {
        __syncthreads();
        const float* src = ((cb < 4) ? A : Bb) + ((size_t)b * C + (cb & 3) * 32) * HW + hw0;
        #pragma unroll
        for (int r = 0; r < 4; r++) {
            int idx = tid + 256 * r;
            int ch = idx >> 5, pg = idx & 31;
            float4 v = *(const float4*)(src + (size_t)ch * HW + pg * 4);
            As[ch][pg * 4 + 0] = to_tf32(v.x);
            As[ch][pg * 4 + 1] = to_tf32(v.y);
            As[ch][pg * 4 + 2] = to_tf32(v.z);
            As[ch][pg * 4 + 3] = to_tf32(v.w);
        }
        #pragma unroll
        for (int r = 0; r < 4; r++) {
            int idx = tid + 256 * r;
            int oc = idx >> 3, q = idx & 7;
            float4 v = *(const float4*)(Wal + (size_t)oc * 256 + cb * 32 + q * 4);
            Bs[oc][q * 4 + 0] = to_tf32(v.x);
            Bs[oc][q * 4 + 1] = to_tf32(v.y);
            Bs[oc][q * 4 + 2] = to_tf32(v.z);
            Bs[oc][q * 4 + 3] = to_tf32(v.w);
        }
        __syncthreads();
        #pragma unroll
        for (int kk = 0; kk < 4; kk++) {
            uint32_t afr[2][4];
            int krow = kk * 8 + (lane & 3);
            #pragma unroll
            for (int mt = 0; mt < 2; mt++) {
                int m0 = mg * 32 + mt * 16 + (lane >> 2);
                afr[mt][0] = __float_as_uint(As[krow][m0]);
                afr[mt][1] = __float_as_uint(As[krow][m0 + 8]);
                afr[mt][2] = __float_as_uint(As[krow + 4][m0]);
                afr[mt][3] = __float_as_uint(As[krow + 4][m0 + 8]);
            }
            #pragma unroll
            for (int nt = 0; nt < 8; nt++) {
                int nb = (ng * 64 + nt * 8 + (lane >> 2)) * 36 + krow;
                uint32_t b0 = __float_as_uint(Bs[0][nb]);
                uint32_t b1 = __float_as_uint(Bs[0][nb + 4]);
                mma_tf32(acc[0][nt], afr[0], b0, b1);
                mma_tf32(acc[1][nt], afr[1], b0, b1);
            }
        }
    }
    #pragma unroll
    for (int mt = 0; mt < 2; mt++)
        #pragma unroll
        for (int nt = 0; nt < 8; nt++)
            #pragma unroll
            for (int i = 0; i < 4; i++) {
                int px = mg * 32 + mt * 16 + (lane >> 2) + ((i >> 1) * 8);
                int oc = ng * 64 + nt * 8 + 2 * (lane & 3) + (i & 1);
                out[((size_t)b * C + oc) * HW + hw0 + px] = acc[mt][nt][i];
            }
}

// ============================================================
// 5) fold up_w2 into up_w1 (tf32-rounded), permuted K layout
// ============================================================
__global__ void wcomb_kernel(const float* __restrict__ up_w1,   // [512,128,3,3]
                             const float* __restrict__ up_w2) { // [64,128]
    int idx = blockIdx.x * 256 + threadIdx.x;
    if (idx >= 256 * C * 9) return;
    int kprime = idx % 1152;
    int oc = idx / 1152;
    int cb = kprime / 288;
    int rem = kprime % 288;
    int tap = rem / 32;
    int cin = cb * 32 + (rem & 31);
    int o = oc >> 2, pos = oc & 3;
    float acc = 0.f;
    #pragma unroll 8
    for (int ci = 0; ci < C; ci++)
        acc += up_w2[o * C + ci] * up_w1[((size_t)(ci * 4 + pos) * C + cin) * 9 + tap];
    g_wcomb[idx] = to_tf32(acc);
}

// ============================================================
// 6) big conv 3x3 via tf32 mma.sync (implicit GEMM, A from halo)
// ============================================================
__global__ __launch_bounds__(256, 2)
void bigconv_mma_kernel(const float* __restrict__ fin, float* __restrict__ outp) {
    __shared__ float XH[32 * 201];   // [cin 32][halo 10x18, row stride 20]
    __shared__ float Bs[128 * 36];   // [oc 128][k 32 + pad 4]

    int tid = threadIdx.x;
    int wid = tid >> 5, lane = tid & 31;
    int b = blockIdx.z, oh = blockIdx.y, st = blockIdx.x;
    int ty0 = (st >> 2) * 8, tx0 = (st & 3) * 16;
    int mg = wid >> 1, ng = wid & 1;

    int h0[2], h1[2];
    #pragma unroll
    for (int mt = 0; mt < 2; mt++) {
        int p0 = mg * 32 + mt * 16 + (lane >> 2);
        int p1 = p0 + 8;
        h0[mt] = (p0 >> 4) * 20 + (p0 & 15);
        h1[mt] = (p1 >> 4) * 20 + (p1 & 15);
    }

    float acc[2][8][4];
    #pragma unroll
    for (int mt = 0; mt < 2; mt++)
        #pragma unroll
        for (int nt = 0; nt < 8; nt++)
            #pragma unroll
            for (int i = 0; i < 4; i++) acc[mt][nt][i] = 0.f;

    const float* wbase = g_wcomb + (size_t)(oh * 128) * 1152;

    for (int cb = 0; cb < 4; cb++) {
        for (int tap = 0; tap < 9; tap++) {
            __syncthreads();
            if (tap == 0) {
                for (int i = tid; i < 32 * 180; i += 256) {
                    int cw = i / 180, rem = i % 180, r = rem / 18, c = rem % 18;
                    int gy = ty0 + r - 1, gx = tx0 + c - 1;
                    float v = 0.f;
                    if (gy >= 0 && gy < H && gx >= 0 && gx < W)
                        v = fin[((size_t)b * C + cb * 32 + cw) * HW + gy * W + gx];
                    XH[cw * 201 + r * 20 + c] = to_tf32(v);
                }
            }
            {
                const float4* src = (const float4*)(wbase + cb * 288 + tap * 32);
                int n = tid >> 3, q = tid & 7;
                #pragma unroll
                for (int r = 0; r < 4; r++) {
                    int nn = n + 32 * r;
                    float4 v = src[(size_t)nn * 288 + q];
                    float* d = &Bs[nn * 36 + q * 4];
                    d[0] = v.x; d[1] = v.y; d[2] = v.z; d[3] = v.w;
                }
            }
            __syncthreads();

            int d = (tap / 3) * 20 + (tap % 3);
            #pragma unroll
            for (int kk = 0; kk < 4; kk++) {
                uint32_t afr[2][4];
                int c0 = (kk * 8 + (lane & 3)) * 201 + d;
                #pragma unroll
                for (int mt = 0; mt < 2; mt++) {
                    afr[mt][0] = __float_as_uint(XH[c0 + h0[mt]]);
                    afr[mt][1] = __float_as_uint(XH[c0 + h1[mt]]);
                    afr[mt][2] = __float_as_uint(XH[c0 + 4 * 201 + h0[mt]]);
                    afr[mt][3] = __float_as_uint(XH[c0 + 4 * 201 + h1[mt]]);
                }
                #pragma unroll
                for (int nt = 0; nt < 8; nt++) {
                    int nb = (ng * 64 + nt * 8 + (lane >> 2)) * 36 + kk * 8 + (lane & 3);
                    uint32_t b0 = __float_as_uint(Bs[nb]);
                    uint32_t b1 = __float_as_uint(Bs[nb + 4]);
                    mma_tf32(acc[0][nt], afr[0], b0, b1);
                    mma_tf32(acc[1][nt], afr[1], b0, b1);
                }
            }
        }
    }

    #pragma unroll
    for (int mt = 0; mt < 2; mt++) {
        #pragma unroll
        for (int nt = 0; nt < 8; nt++) {
            #pragma unroll
            for (int i = 0; i < 4; i++) {
                int px = mg * 32 + mt * 16 + (lane >> 2) + ((i >> 1) * 8);
                int oc = oh * 128 + ng * 64 + nt * 8 + 2 * (lane & 3) + (i & 1);
                int gy = ty0 + (px >> 4), gx = tx0 + (px & 15);
                int o = oc >> 2, r1 = (oc >> 1) & 1, r2 = oc & 1;
                outp[(((size_t)b * OUT + o) * H2 + 2 * gy + r1) * W2 + 2 * gx + r2] =
                    acc[mt][nt][i];
            }
        }
    }
}

// ============================================================
// 7) refine conv1 via tf32 mma: 64->8 3x3 at 128x128, relu.
//    tile 8x16 px per CTA; each warp one row of 16 px (m16, n8).
// ============================================================
__global__ __launch_bounds__(256, 2)
void reconv1_mma_kernel(const float* __restrict__ up,
                        const float* __restrict__ w) {   // [8,64,3,3]
    __shared__ float XH[32 * 201];
    __shared__ float Ws[8][584];    // [oc][k' = cb*288+tap*32+cin]
    int tid = threadIdx.x;
    int wid = tid >> 5, lane = tid & 31;
    int b = blockIdx.y, st = blockIdx.x;
    int ty0 = (st >> 3) * 8, tx0 = (st & 7) * 16;

    for (int i = tid; i < 8 * 576; i += 256) {
        int o = i / 576, kp = i % 576;
        int cb = kp / 288, rem = kp % 288, tap = rem / 32, ci = rem & 31;
        Ws[o][kp] = to_tf32(w[((o * OUT) + cb * 32 + ci) * 9 + tap]);
    }

    int hA = wid * 20 + (lane >> 2);
    float acc[4] = {0.f, 0.f, 0.f, 0.f};

    for (int cb = 0; cb < 2; cb++) {
        __syncthreads();
        for (int i = tid; i < 32 * 180; i += 256) {
            int cw = i / 180, rem = i % 180, r = rem / 18, c = rem % 18;
            int gy = ty0 + r - 1, gx = tx0 + c - 1;
            float v = 0.f;
            if (gy >= 0 && gy < H2 && gx >= 0 && gx < W2)
                v = up[(((size_t)b * OUT + cb * 32 + cw) * H2 + gy) * W2 + gx];
            XH[cw * 201 + r * 20 + c] = to_tf32(v);
        }
        __syncthreads();
        for (int tap = 0; tap < 9; tap++) {
            int d = (tap / 3) * 20 + (tap % 3);
            #pragma unroll
            for (int kk = 0; kk < 4; kk++) {
                int cin = kk * 8 + (lane & 3);
                uint32_t afr[4];
                afr[0] = __float_as_uint(XH[cin * 201 + d + hA]);
                afr[1] = __float_as_uint(XH[cin * 201 + d + hA + 8]);
                afr[2] = __float_as_uint(XH[(cin + 4) * 201 + d + hA]);
                afr[3] = __float_as_uint(XH[(cin + 4) * 201 + d + hA + 8]);
                int kp = cb * 288 + tap * 32 + cin;
                uint32_t b0 = __float_as_uint(Ws[lane >> 2][kp]);
                uint32_t b1 = __float_as_uint(Ws[lane >> 2][kp + 4]);
                mma_tf32(acc, afr, b0, b1);
            }
        }
    }
    #pragma unroll
    for (int i = 0; i < 4; i++) {
        int oc = 2 * (lane & 3) + (i & 1);
        int gx = tx0 + (lane >> 2) + (i >> 1) * 8;
        int gy = ty0 + wid;
        g_re[(((size_t)b * RE + oc) * H2 + gy) * W2 + gx] = fmaxf(acc[i], 0.f);
    }
}

// ============================================================
// 8) refine conv2 via tf32 mma + residual add: 8->64 3x3 at 128x128.
//    tile 128 px x 64 oc per CTA.
// ============================================================
__global__ __launch_bounds__(256, 2)
void reconv2_mma_kernel(const float* __restrict__ w,   // [64,8,3,3]
                        float* __restrict__ outp) {
    __shared__ float XH[8 * 201];
    __shared__ float Ws[64][76];    // [oc][tap*8+cin]
    int tid = threadIdx.x;
    int wid = tid >> 5, lane = tid & 31;
    int b = blockIdx.y, st = blockIdx.x;
    int ty0 = (st >> 3) * 8, tx0 = (st & 7) * 16;
    int mg = wid >> 1, ng = wid & 1;

    for (int i = tid; i < 64 * 72; i += 256) {
        int o = i / 72, kt = i % 72;
        int tap = kt >> 3, ci = kt & 7;
        Ws[o][kt] = to_tf32(w[(o * RE + ci) * 9 + tap]);
    }
    for (int i = tid; i < 8 * 180; i += 256) {
        int cw = i / 180, rem = i % 180, r = rem / 18, c = rem % 18;
        int gy = ty0 + r - 1, gx = tx0 + c - 1;
        float v = 0.f;
        if (gy >= 0 && gy < H2 && gx >= 0 && gx < W2)
            v = g_re[(((size_t)b * RE + cw) * H2 + gy) * W2 + gx];
        XH[cw * 201 + r * 20 + c] = to_tf32(v);
    }
    __syncthreads();

    int h0[2], h1[2];
    #pragma unroll
    for (int mt = 0; mt < 2; mt++) {
        int p0 = mg * 32 + mt * 16 + (lane >> 2);
        int p1 = p0 + 8;
        h0[mt] = (p0 >> 4) * 20 + (p0 & 15);
        h1[mt] = (p1 >> 4) * 20 + (p1 & 15);
    }

    float acc[2][4][4];
    #pragma unroll
    for (int mt = 0; mt < 2; mt++)
        #pragma unroll
        for (int nt = 0; nt < 4; nt++)
            #pragma unroll
            for (int i = 0; i < 4; i++) acc[mt][nt][i] = 0.f;

    #pragma unroll
    for (int tap = 0; tap < 9; tap++) {
        int d = (tap / 3) * 20 + (tap % 3);
        uint32_t afr[2][4];
        int c0 = (lane & 3) * 201 + d;
        #pragma unroll
        for (int mt = 0; mt < 2; mt++) {
            afr[mt][0] = __float_as_uint(XH[c0 + h0[mt]]);
            afr[mt][1] = __float_as_uint(XH[c0 + h1[mt]]);
            afr[mt][2] = __float_as_uint(XH[c0 + 4 * 201 + h0[mt]]);
            afr[mt][3] = __float_as_uint(XH[c0 + 4 * 201 + h1[mt]]);
        }
        #pragma unroll
        for (int nt = 0; nt < 4; nt++) {
            int n = ng * 32 + nt * 8 + (lane >> 2);
            uint32_t b0 = __float_as_uint(Ws[n][tap * 8 + (lane & 3)]);
            uint32_t b1 = __float_as_uint(Ws[n][tap * 8 + (lane & 3) + 4]);
            mma_tf32(acc[0][nt], afr[0], b0, b1);
            mma_tf32(acc[1][nt], afr[1], b0, b1);
        }
    }

    #pragma unroll
    for (int mt = 0; mt < 2; mt++)
        #pragma unroll
        for (int nt = 0; nt < 4; nt++)
            #pragma unroll
            for (int i = 0; i < 4; i++) {
                int px = mg * 32 + mt * 16 + (lane >> 2) + ((i >> 1) * 8);
                int oc = ng * 32 + nt * 8 + 2 * (lane & 3) + (i & 1);
                int gy = ty0 + (px >> 4), gx = tx0 + (px & 15);
                size_t idx = (((size_t)b * OUT + oc) * H2 + gy) * W2 + gx;
                outp[idx] = outp[idx] + acc[mt][nt][i];
            }
}

// ============================================================
extern "C" void kernel_launch(void* const* d_in, const int* in_sizes, int n_in,
                              void* d_out, int out_size) {
    const float* x1     = (const float*)d_in[0];
    const float* x2     = (const float*)d_in[1];
    const float* d1_w1  = (const float*)d_in[2];
    const float* d1_w2  = (const float*)d_in[3];
    const float* d2_w1  = (const float*)d_in[4];
    const float* d2_w2  = (const float*)d_in[5];
    const float* alignw = (const float*)d_in[6];
    const float* up_w1  = (const float*)d_in[7];
    const float* up_w2  = (const float*)d_in[8];
    const float* re_w1  = (const float*)d_in[9];
    const float* re_w2  = (const float*)d_in[10];
    float* outp = (float*)d_out;

    void *pv, *wkv, *t1v, *av, *bv, *fv;
    cudaGetSymbolAddress(&pv, g_pooled);
    cudaGetSymbolAddress(&wkv, g_wk);
    cudaGetSymbolAddress(&t1v, g_t1);
    cudaGetSymbolAddress(&av, g_a);
    cudaGetSymbolAddress(&bv, g_b);
    cudaGetSymbolAddress(&fv, g_fused);
    float* pooled = (float*)pv;
    float* wkb    = (float*)wkv;
    float* t1     = (float*)t1v;
    float* a      = (float*)av;
    float* bb     = (float*)bv;
    float* fused  = (float*)fv;

    // fold up_w2 into up_w1 (tf32, permuted-K layout)
    wcomb_kernel<<<(256 * C * 9 + 255) / 256, 256>>>(up_w1, up_w2);

    // dynamic_block(x1) -> a    (pool of stage-1 output fused into dsc_apply)
    pool_kernel<<<B * C, 256>>>(x1, pooled);
    mlp_kernel<<<B, C>>>(pooled, d1_w1, d1_w2, wkb);
    dsc_apply_kernel<<<B * C, 256>>>(x1, wkb, t1, 1, pooled);
    mlp_kernel<<<B, C>>>(pooled, d2_w1, d2_w2, wkb);
    dsc_apply_kernel<<<B * C, 256>>>(t1, wkb, a, 0, nullptr);

    // dynamic_block(x2) -> bb
    pool_kernel<<<B * C, 256>>>(x2, pooled);
    mlp_kernel<<<B, C>>>(pooled, d1_w1, d1_w2, wkb);
    dsc_apply_kernel<<<B * C, 256>>>(x2, wkb, t1, 1, pooled);
    mlp_kernel<<<B, C>>>(pooled, d2_w1, d2_w2, wkb);
    dsc_apply_kernel<<<B * C, 256>>>(t1, wkb, bb, 0, nullptr);

    // align 1x1 over concat (tf32 mma)
    fuse_mma_kernel<<<dim3(32, B), 256>>>(a, bb, alignw, fused);

    // conv3x3 (folded with up_w2) + pixel shuffle via tf32 mma
    bigconv_mma_kernel<<<dim3(32, 2, B), 256>>>(fused, outp);

    // refine (tf32 mma)
    reconv1_mma_kernel<<<dim3(128, B), 256>>>(outp, re_w1);
    reconv2_mma_kernel<<<dim3(128, B), 256>>>(re_w2, outp);
}